// round 8
// baseline (speedup 1.0000x reference)
#include <cuda_runtime.h>
#include <cuda_bf16.h>
#include <cstdint>

#define O_NUM 50000
#define T_NUM 200000
#define N_NUM (O_NUM + T_NUM)
#define D_DIM 128
#define NPART 196           // ceil(O_NUM/256)
#define WBLK  64            // wconv blocks (16384/256)
#define RSQRT2F 0.7071067811865476f

// ---------------- scratch (no allocations allowed) ----------------
__device__ __nv_bfloat16 g_yh[(size_t)N_NUM * D_DIM];   // rows >= T_NUM unused
__device__ __nv_bfloat16 g_yl[(size_t)N_NUM * D_DIM];
__device__ __nv_bfloat16 g_wh[D_DIM * D_DIM];
__device__ __nv_bfloat16 g_wl[D_DIM * D_DIM];
__device__ float     g_dinv[O_NUM];
__device__ int       g_counts[O_NUM];
__device__ int       g_offs[O_NUM + 1];
__device__ int       g_cursor[O_NUM];
__device__ int       g_sorted[T_NUM];
__device__ volatile int g_scan_flag[NPART];
__device__ volatile int g_scan_incl[NPART];
__device__ int       g_stride;
__device__ int       g_doff;

__device__ __forceinline__ int edge_src(const int* e32, int t, int stride) {
    return __ldg(e32 + (size_t)stride * t);
}
__device__ __forceinline__ int edge_dst(const int* e32, int t, int stride, int doff) {
    return __ldg(e32 + (size_t)stride * t + doff);
}
__device__ __forceinline__ const float* row_ptr(int k, const float* obj, const float* pred) {
    return (k < O_NUM) ? (obj + (size_t)k * D_DIM) : (pred + (size_t)(k - O_NUM) * D_DIM);
}

// ---------------- K1: prep = zero counters/flags + W split + dtype detect ----------------
__global__ void prep_kernel(const float* __restrict__ W, const int* __restrict__ e32) {
    int b = blockIdx.x;
    if (b < NPART) {
        int i = b * 256 + threadIdx.x;
        if (i < O_NUM) { g_counts[i] = 0; g_cursor[i] = 0; }
        if (threadIdx.x == 0) { g_scan_flag[b] = 0; g_scan_incl[b] = 0; }
    } else if (b < NPART + WBLK) {
        int i = (b - NPART) * 256 + threadIdx.x;
        float w = W[i];
        __nv_bfloat16 h = __float2bfloat16(w);
        g_wh[i] = h;
        g_wl[i] = __float2bfloat16(w - __bfloat162float(h));
    } else {
        if (threadIdx.x < 32) {
            int acc = 0;
            for (int i = threadIdx.x; i < 4096; i += 32) acc |= e32[2 * i + 1];
            #pragma unroll
            for (int off = 16; off; off >>= 1) acc |= __shfl_xor_sync(0xFFFFFFFFu, acc, off);
            if (threadIdx.x == 0) {
                g_stride = acc ? 2 : 4;
                g_doff   = acc ? 1 : 2;
            }
        }
    }
}

// ---------------- K2: histogram of edges[:,1] ----------------
__global__ void hist_kernel(const int* __restrict__ e32) {
    int t = blockIdx.x * blockDim.x + threadIdx.x;
    if (t < T_NUM) {
        int d = edge_dst(e32, t, g_stride, g_doff);
        atomicAdd(&g_counts[d], 1);
    }
}

// ---------------- K3: single-launch decoupled scan + dinv ----------------
__global__ __launch_bounds__(256) void scan_kernel() {
    int b = blockIdx.x, t = threadIdx.x;
    int i = b * 256 + t;
    int lane = t & 31, w = t >> 5;
    int v = (i < O_NUM) ? g_counts[i] : 0;

    int iv = v;
    #pragma unroll
    for (int off = 1; off < 32; off <<= 1) {
        int n = __shfl_up_sync(0xFFFFFFFFu, iv, off);
        if (lane >= off) iv += n;
    }
    __shared__ int ws[8];
    if (lane == 31) ws[w] = iv;
    __syncthreads();
    if (w == 0 && lane < 8) {
        int x = ws[lane];
        #pragma unroll
        for (int off = 1; off < 8; off <<= 1) {
            int n = __shfl_up_sync(0x000000FFu, x, off);
            if (lane >= off) x += n;
        }
        ws[lane] = x;
    }
    __syncthreads();
    int excl = iv - v + (w ? ws[w - 1] : 0);
    int tot  = ws[7];

    __shared__ int base_s;
    if (t == 0) {
        int base = 0;
        if (b > 0) {
            while (g_scan_flag[b - 1] == 0) { }
            __threadfence();
            base = g_scan_incl[b - 1];
        }
        g_scan_incl[b] = base + tot;
        __threadfence();
        g_scan_flag[b] = 1;
        base_s = base;
        if (b == NPART - 1) g_offs[O_NUM] = base + tot;
    }
    __syncthreads();
    int base = base_s;

    if (i < O_NUM) {
        g_offs[i] = excl + base;
        g_dinv[i] = rsqrtf(2.0f + (float)v);
    }
}

// ---------------- K4: easy rows n in [O_NUM, T_NUM): self + one obj gather ----------------
__global__ __launch_bounds__(256) void agg_easy_kernel(const float* __restrict__ obj,
                                                       const float* __restrict__ pred,
                                                       const int* __restrict__ e32) {
    int gwarp = (blockIdx.x * blockDim.x + threadIdx.x) >> 5;
    int lane  = threadIdx.x & 31;
    if (gwarp >= T_NUM - O_NUM) return;
    int n = O_NUM + gwarp;                    // node index, pred row = gwarp

    // both loads issued back-to-back (independent)
    const float4* xn = reinterpret_cast<const float4*>(pred + (size_t)gwarp * D_DIM);
    float4 a = __ldg(xn + lane);
    int s = edge_src(e32, n, g_stride);
    float ds = g_dinv[s];
    const float4* xs = reinterpret_cast<const float4*>(obj + (size_t)s * D_DIM);
    float4 v = __ldg(xs + lane);

    const float dn = RSQRT2F;
    float4 acc;
    acc.x = (fmaf(v.x, ds, a.x * dn)) * dn;
    acc.y = (fmaf(v.y, ds, a.y * dn)) * dn;
    acc.z = (fmaf(v.z, ds, a.z * dn)) * dn;
    acc.w = (fmaf(v.w, ds, a.w * dn)) * dn;

    float v4[4] = {acc.x, acc.y, acc.z, acc.w};
    alignas(8) __nv_bfloat16 h[4];
    alignas(8) __nv_bfloat16 l[4];
    #pragma unroll
    for (int q = 0; q < 4; q++) {
        h[q] = __float2bfloat16(v4[q]);
        l[q] = __float2bfloat16(v4[q] - __bfloat162float(h[q]));
    }
    size_t base = (size_t)n * D_DIM + lane * 4;
    *reinterpret_cast<uint2*>(g_yh + base) = *reinterpret_cast<const uint2*>(h);
    *reinterpret_cast<uint2*>(g_yl + base) = *reinterpret_cast<const uint2*>(l);
}

// ---------------- K5: counting-sort scatter ----------------
__global__ void csr_scatter_kernel(const int* __restrict__ e32) {
    int t = blockIdx.x * blockDim.x + threadIdx.x;
    if (t < T_NUM) {
        int d = edge_dst(e32, t, g_stride, g_doff);
        int pos = g_offs[d] + atomicAdd(&g_cursor[d], 1);
        g_sorted[pos] = t;
    }
}

// ---------------- K6: hard rows n < O_NUM: self + obj gather + bucket ----------------
__global__ __launch_bounds__(256) void agg_hard_kernel(const float* __restrict__ obj,
                                                       const float* __restrict__ pred,
                                                       const int* __restrict__ e32) {
    int n = (blockIdx.x * blockDim.x + threadIdx.x) >> 5;
    int lane  = threadIdx.x & 31;
    if (n >= O_NUM) return;
    float dn = g_dinv[n];

    const float4* xn = reinterpret_cast<const float4*>(obj + (size_t)n * D_DIM);
    float4 a = __ldg(xn + lane);

    int s = edge_src(e32, n, g_stride);
    float ds = g_dinv[s];
    const float4* xs = reinterpret_cast<const float4*>(obj + (size_t)s * D_DIM);
    float4 v1 = __ldg(xs + lane);

    float4 acc;
    acc.x = fmaf(v1.x, ds, a.x * dn);
    acc.y = fmaf(v1.y, ds, a.y * dn);
    acc.z = fmaf(v1.z, ds, a.z * dn);
    acc.w = fmaf(v1.w, ds, a.w * dn);

    int beg = g_offs[n];
    int cnt = g_offs[n + 1] - beg;
    for (int bb = 0; bb < cnt; bb += 8) {
        int m = cnt - bb; if (m > 8) m = 8;
        int   kid = 0;
        float dkl = 0.0f;
        if (lane < m) {
            kid = g_sorted[beg + bb + lane];
            dkl = (kid < O_NUM) ? g_dinv[kid] : RSQRT2F;
        }
        #pragma unroll
        for (int i = 0; i < 8; i++) {
            if (i >= m) break;
            int   k  = __shfl_sync(0xFFFFFFFFu, kid, i);
            float dk = __shfl_sync(0xFFFFFFFFu, dkl, i);
            const float4* xk = reinterpret_cast<const float4*>(row_ptr(k, obj, pred));
            float4 v = __ldg(xk + lane);
            acc.x = fmaf(v.x, dk, acc.x);
            acc.y = fmaf(v.y, dk, acc.y);
            acc.z = fmaf(v.z, dk, acc.z);
            acc.w = fmaf(v.w, dk, acc.w);
        }
    }

    acc.x *= dn; acc.y *= dn; acc.z *= dn; acc.w *= dn;

    float v4[4] = {acc.x, acc.y, acc.z, acc.w};
    alignas(8) __nv_bfloat16 h[4];
    alignas(8) __nv_bfloat16 l[4];
    #pragma unroll
    for (int i = 0; i < 4; i++) {
        h[i] = __float2bfloat16(v4[i]);
        l[i] = __float2bfloat16(v4[i] - __bfloat162float(h[i]));
    }
    size_t base = (size_t)n * D_DIM + lane * 4;
    *reinterpret_cast<uint2*>(g_yh + base) = *reinterpret_cast<const uint2*>(h);
    *reinterpret_cast<uint2*>(g_yl + base) = *reinterpret_cast<const uint2*>(l);
}

// ---------------- K7: out = Y @ W^T + b, 64-row tiles, 2 CTAs/SM ----------------
__device__ __forceinline__ void mma16816(float c[4], const uint32_t a[4], const uint32_t b[2]) {
    asm("mma.sync.aligned.m16n8k16.row.col.f32.bf16.bf16.f32 "
        "{%0,%1,%2,%3}, {%4,%5,%6,%7}, {%8,%9}, {%0,%1,%2,%3};"
        : "+f"(c[0]), "+f"(c[1]), "+f"(c[2]), "+f"(c[3])
        : "r"(a[0]), "r"(a[1]), "r"(a[2]), "r"(a[3]), "r"(b[0]), "r"(b[1]));
}

#define LDSY 136
#define SMEM_W_HALF (128 * LDSY)
#define SMEM_Y_HALF (64 * LDSY)
#define GEMM_SMEM_BYTES ((2 * SMEM_W_HALF + 2 * SMEM_Y_HALF) * 2)   // ~104.4 KB

__device__ __forceinline__ uint32_t lds32(const __nv_bfloat16* p) {
    return *reinterpret_cast<const uint32_t*>(p);
}

extern __shared__ char sm_raw[];

__global__ __launch_bounds__(256) void gemm_mma_kernel(const float* __restrict__ pred,
                                                       const float* __restrict__ bias,
                                                       float* __restrict__ out) {
    __nv_bfloat16* sWh = reinterpret_cast<__nv_bfloat16*>(sm_raw);
    __nv_bfloat16* sWl = sWh + SMEM_W_HALF;
    __nv_bfloat16* sYh = sWl + SMEM_W_HALF;
    __nv_bfloat16* sYl = sYh + SMEM_Y_HALF;

    int tid  = threadIdx.x;
    int warp = tid >> 5, lane = tid & 31;
    int g  = lane >> 2;
    int tg = lane & 3;
    int rowbase = blockIdx.x * 64;

    // stage W (both halves), coalesced uint4
    #pragma unroll
    for (int it = 0; it < 8; it++) {
        int r = it * 16 + (tid >> 4);
        int cseg = tid & 15;
        uint4 vh = *reinterpret_cast<const uint4*>(g_wh + r * D_DIM + cseg * 8);
        uint4 vl = *reinterpret_cast<const uint4*>(g_wl + r * D_DIM + cseg * 8);
        *reinterpret_cast<uint4*>(sWh + r * LDSY + cseg * 8) = vh;
        *reinterpret_cast<uint4*>(sWl + r * LDSY + cseg * 8) = vl;
    }

    if (rowbase >= T_NUM) {
        // identity rows: y = x (pred), split on the fly (deg = 1)
        #pragma unroll
        for (int it = 0; it < 4; it++) {
            int r = it * 16 + (tid >> 4);
            int cseg = tid & 15;
            int grow = rowbase + r;
            alignas(16) __nv_bfloat16 h[8];
            alignas(16) __nv_bfloat16 l[8];
            if (grow < N_NUM) {
                const float* src = pred + (size_t)(grow - O_NUM) * D_DIM + cseg * 8;
                #pragma unroll
                for (int q = 0; q < 8; q++) {
                    float f = __ldg(src + q);
                    h[q] = __float2bfloat16(f);
                    l[q] = __float2bfloat16(f - __bfloat162float(h[q]));
                }
            } else {
                #pragma unroll
                for (int q = 0; q < 8; q++) { h[q] = __float2bfloat16(0.f); l[q] = h[q]; }
            }
            *reinterpret_cast<uint4*>(sYh + r * LDSY + cseg * 8) = *reinterpret_cast<const uint4*>(h);
            *reinterpret_cast<uint4*>(sYl + r * LDSY + cseg * 8) = *reinterpret_cast<const uint4*>(l);
        }
    } else {
        #pragma unroll
        for (int it = 0; it < 4; it++) {
            int r = it * 16 + (tid >> 4);
            int cseg = tid & 15;
            int grow = rowbase + r;
            uint4 vh = *reinterpret_cast<const uint4*>(g_yh + (size_t)grow * D_DIM + cseg * 8);
            uint4 vl = *reinterpret_cast<const uint4*>(g_yl + (size_t)grow * D_DIM + cseg * 8);
            *reinterpret_cast<uint4*>(sYh + r * LDSY + cseg * 8) = vh;
            *reinterpret_cast<uint4*>(sYl + r * LDSY + cseg * 8) = vl;
        }
    }
    __syncthreads();

    int band = warp >> 1;
    int ch   = warp & 1;

    const __nv_bfloat16* aH0 = sYh + (band * 16 + g) * LDSY;
    const __nv_bfloat16* aL0 = sYl + (band * 16 + g) * LDSY;

    float c[8][4];
    #pragma unroll
    for (int n = 0; n < 8; n++)
        #pragma unroll
        for (int q = 0; q < 4; q++) c[n][q] = 0.0f;

    #pragma unroll
    for (int kt = 0; kt < 8; kt++) {
        int k = kt * 16;
        uint32_t ah[4], al[4];
        ah[0] = lds32(aH0 + k + tg * 2);
        ah[1] = lds32(aH0 + 8 * LDSY + k + tg * 2);
        ah[2] = lds32(aH0 + k + 8 + tg * 2);
        ah[3] = lds32(aH0 + 8 * LDSY + k + 8 + tg * 2);
        al[0] = lds32(aL0 + k + tg * 2);
        al[1] = lds32(aL0 + 8 * LDSY + k + tg * 2);
        al[2] = lds32(aL0 + k + 8 + tg * 2);
        al[3] = lds32(aL0 + 8 * LDSY + k + 8 + tg * 2);

        #pragma unroll
        for (int n = 0; n < 8; n++) {
            int cw = ch * 64 + n * 8 + g;
            const __nv_bfloat16* bH = sWh + cw * LDSY + k + tg * 2;
            const __nv_bfloat16* bL = sWl + cw * LDSY + k + tg * 2;
            uint32_t bh[2] = { lds32(bH), lds32(bH + 8) };
            uint32_t bl[2] = { lds32(bL), lds32(bL + 8) };
            mma16816(c[n], ah, bh);
            mma16816(c[n], al, bh);
            mma16816(c[n], ah, bl);
        }
    }

    int r0 = rowbase + band * 16 + g;
    int r1 = r0 + 8;
    #pragma unroll
    for (int n = 0; n < 8; n++) {
        int col = ch * 64 + n * 8 + tg * 2;
        float2 bb = *reinterpret_cast<const float2*>(bias + col);
        if (r0 < N_NUM) {
            float2 o = make_float2(c[n][0] + bb.x, c[n][1] + bb.y);
            *reinterpret_cast<float2*>(out + (size_t)r0 * D_DIM + col) = o;
        }
        if (r1 < N_NUM) {
            float2 o = make_float2(c[n][2] + bb.x, c[n][3] + bb.y);
            *reinterpret_cast<float2*>(out + (size_t)r1 * D_DIM + col) = o;
        }
    }
}

// ---------------- launch ----------------
extern "C" void kernel_launch(void* const* d_in, const int* in_sizes, int n_in,
                              void* d_out, int out_size) {
    const float* obj   = (const float*)d_in[0];
    const float* pred  = (const float*)d_in[1];
    const int*   e32   = (const int*)d_in[2];
    const float* W     = (const float*)d_in[3];
    const float* bias  = (const float*)d_in[4];
    float*       out   = (float*)d_out;

    cudaFuncSetAttribute(gemm_mma_kernel,
                         cudaFuncAttributeMaxDynamicSharedMemorySize, GEMM_SMEM_BYTES);

    prep_kernel<<<NPART + WBLK + 1, 256>>>(W, e32);                         // 1
    hist_kernel<<<(T_NUM + 255) / 256, 256>>>(e32);                         // 2
    scan_kernel<<<NPART, 256>>>();                                          // 3
    agg_easy_kernel<<<(T_NUM - O_NUM + 7) / 8, 256>>>(obj, pred, e32);      // 4 <- ncu slot
    csr_scatter_kernel<<<(T_NUM + 255) / 256, 256>>>(e32);                  // 5
    agg_hard_kernel<<<(O_NUM + 7) / 8, 256>>>(obj, pred, e32);              // 6
    gemm_mma_kernel<<<(N_NUM + 63) / 64, 256, GEMM_SMEM_BYTES>>>(pred, bias, out);  // 7
}

// round 9
// speedup vs baseline: 2.1779x; 2.1779x over previous
#include <cuda_runtime.h>
#include <cuda_bf16.h>
#include <cstdint>

#define O_NUM 50000
#define T_NUM 200000
#define N_NUM (O_NUM + T_NUM)
#define D_DIM 128
#define NPART 196           // ceil(O_NUM/256)
#define WBLK  64            // wconv blocks (16384/256)
#define RSQRT2F 0.7071067811865476f

// ---------------- scratch (no allocations allowed) ----------------
__device__ __nv_bfloat16 g_yh[(size_t)N_NUM * D_DIM];   // rows >= T_NUM unused
__device__ __nv_bfloat16 g_yl[(size_t)N_NUM * D_DIM];
__device__ __nv_bfloat16 g_wh[D_DIM * D_DIM];
__device__ __nv_bfloat16 g_wl[D_DIM * D_DIM];
__device__ float     g_dinv[O_NUM];
__device__ int       g_counts[O_NUM];
__device__ int       g_offs[O_NUM + 1];
__device__ int       g_cursor[O_NUM];
__device__ int       g_sorted[T_NUM];
__device__ int       g_part[NPART];
__device__ int       g_stride;
__device__ int       g_doff;

__device__ __forceinline__ int edge_src(const int* e32, int t, int stride) {
    return __ldg(e32 + (size_t)stride * t);
}
__device__ __forceinline__ int edge_dst(const int* e32, int t, int stride, int doff) {
    return __ldg(e32 + (size_t)stride * t + doff);
}
__device__ __forceinline__ const float* row_ptr(int k, const float* obj, const float* pred) {
    return (k < O_NUM) ? (obj + (size_t)k * D_DIM) : (pred + (size_t)(k - O_NUM) * D_DIM);
}

// ---------------- K1: prep = zero counters + W split + dtype detect ----------------
__global__ void prep_kernel(const float* __restrict__ W, const int* __restrict__ e32) {
    int b = blockIdx.x;
    if (b < NPART) {
        int i = b * 256 + threadIdx.x;
        if (i < O_NUM) { g_counts[i] = 0; g_cursor[i] = 0; }
    } else if (b < NPART + WBLK) {
        int i = (b - NPART) * 256 + threadIdx.x;
        float w = W[i];
        __nv_bfloat16 h = __float2bfloat16(w);
        g_wh[i] = h;
        g_wl[i] = __float2bfloat16(w - __bfloat162float(h));
    } else {
        if (threadIdx.x < 32) {
            int acc = 0;
            for (int i = threadIdx.x; i < 4096; i += 32) acc |= e32[2 * i + 1];
            #pragma unroll
            for (int off = 16; off; off >>= 1) acc |= __shfl_xor_sync(0xFFFFFFFFu, acc, off);
            if (threadIdx.x == 0) {
                g_stride = acc ? 2 : 4;
                g_doff   = acc ? 1 : 2;
            }
        }
    }
}

// ---------------- K2: histogram of edges[:,1] ----------------
__global__ void hist_kernel(const int* __restrict__ e32) {
    int t = blockIdx.x * blockDim.x + threadIdx.x;
    if (t < T_NUM) {
        int d = edge_dst(e32, t, g_stride, g_doff);
        atomicAdd(&g_counts[d], 1);
    }
}

// ---------------- K3: per-block exclusive scan ----------------
__global__ __launch_bounds__(256) void scan_block_kernel() {
    int t = threadIdx.x;
    int i = blockIdx.x * 256 + t;
    int lane = t & 31, w = t >> 5;
    int v = (i < O_NUM) ? g_counts[i] : 0;

    int iv = v;
    #pragma unroll
    for (int off = 1; off < 32; off <<= 1) {
        int n = __shfl_up_sync(0xFFFFFFFFu, iv, off);
        if (lane >= off) iv += n;
    }
    __shared__ int ws[8];
    if (lane == 31) ws[w] = iv;
    __syncthreads();
    if (w == 0 && lane < 8) {
        int x = ws[lane];
        #pragma unroll
        for (int off = 1; off < 8; off <<= 1) {
            int n = __shfl_up_sync(0x000000FFu, x, off);
            if (lane >= off) x += n;
        }
        ws[lane] = x;
    }
    __syncthreads();
    int excl = iv - v + (w ? ws[w - 1] : 0);
    if (i < O_NUM) g_offs[i] = excl;
    if (t == 255) g_part[blockIdx.x] = excl + v;
}

// ---------------- K4: fixup (per-block prefix of partials) + dinv ----------------
__global__ __launch_bounds__(256) void scan_fix_kernel() {
    int b = blockIdx.x;
    int t = threadIdx.x;
    int lane = t & 31, w = t >> 5;

    int v = (t < b) ? g_part[t] : 0;
    #pragma unroll
    for (int off = 16; off; off >>= 1) v += __shfl_xor_sync(0xFFFFFFFFu, v, off);
    __shared__ int ws[8];
    if (lane == 0) ws[w] = v;
    __syncthreads();
    __shared__ int base_s;
    if (t == 0) {
        int s = 0;
        #pragma unroll
        for (int q = 0; q < 8; q++) s += ws[q];
        base_s = s;
    }
    __syncthreads();
    int base = base_s;

    int i = b * 256 + t;
    if (i < O_NUM) {
        g_offs[i] += base;
        g_dinv[i] = rsqrtf(2.0f + (float)g_counts[i]);
    }
    if (b == NPART - 1 && t == 0) g_offs[O_NUM] = base + g_part[NPART - 1];
}

// ---------------- K5: easy rows n in [O_NUM, T_NUM): self + one obj gather ----------------
__global__ __launch_bounds__(256) void agg_easy_kernel(const float* __restrict__ obj,
                                                       const float* __restrict__ pred,
                                                       const int* __restrict__ e32) {
    int gwarp = (blockIdx.x * blockDim.x + threadIdx.x) >> 5;
    int lane  = threadIdx.x & 31;
    if (gwarp >= T_NUM - O_NUM) return;
    int n = O_NUM + gwarp;                    // node index, pred row = gwarp

    const float4* xn = reinterpret_cast<const float4*>(pred + (size_t)gwarp * D_DIM);
    float4 a = __ldg(xn + lane);
    int s = edge_src(e32, n, g_stride);
    float ds = g_dinv[s];
    const float4* xs = reinterpret_cast<const float4*>(obj + (size_t)s * D_DIM);
    float4 v = __ldg(xs + lane);

    const float dn = RSQRT2F;
    float4 acc;
    acc.x = (fmaf(v.x, ds, a.x * dn)) * dn;
    acc.y = (fmaf(v.y, ds, a.y * dn)) * dn;
    acc.z = (fmaf(v.z, ds, a.z * dn)) * dn;
    acc.w = (fmaf(v.w, ds, a.w * dn)) * dn;

    float v4[4] = {acc.x, acc.y, acc.z, acc.w};
    alignas(8) __nv_bfloat16 h[4];
    alignas(8) __nv_bfloat16 l[4];
    #pragma unroll
    for (int q = 0; q < 4; q++) {
        h[q] = __float2bfloat16(v4[q]);
        l[q] = __float2bfloat16(v4[q] - __bfloat162float(h[q]));
    }
    size_t base = (size_t)n * D_DIM + lane * 4;
    *reinterpret_cast<uint2*>(g_yh + base) = *reinterpret_cast<const uint2*>(h);
    *reinterpret_cast<uint2*>(g_yl + base) = *reinterpret_cast<const uint2*>(l);
}

// ---------------- K6: counting-sort scatter ----------------
__global__ void csr_scatter_kernel(const int* __restrict__ e32) {
    int t = blockIdx.x * blockDim.x + threadIdx.x;
    if (t < T_NUM) {
        int d = edge_dst(e32, t, g_stride, g_doff);
        int pos = g_offs[d] + atomicAdd(&g_cursor[d], 1);
        g_sorted[pos] = t;
    }
}

// ---------------- K7: hard rows n < O_NUM: self + obj gather + bucket ----------------
__global__ __launch_bounds__(256) void agg_hard_kernel(const float* __restrict__ obj,
                                                       const float* __restrict__ pred,
                                                       const int* __restrict__ e32) {
    int n = (blockIdx.x * blockDim.x + threadIdx.x) >> 5;
    int lane  = threadIdx.x & 31;
    if (n >= O_NUM) return;
    float dn = g_dinv[n];

    const float4* xn = reinterpret_cast<const float4*>(obj + (size_t)n * D_DIM);
    float4 a = __ldg(xn + lane);

    int s = edge_src(e32, n, g_stride);
    float ds = g_dinv[s];
    const float4* xs = reinterpret_cast<const float4*>(obj + (size_t)s * D_DIM);
    float4 v1 = __ldg(xs + lane);

    float4 acc;
    acc.x = fmaf(v1.x, ds, a.x * dn);
    acc.y = fmaf(v1.y, ds, a.y * dn);
    acc.z = fmaf(v1.z, ds, a.z * dn);
    acc.w = fmaf(v1.w, ds, a.w * dn);

    int beg = g_offs[n];
    int cnt = g_offs[n + 1] - beg;
    for (int bb = 0; bb < cnt; bb += 8) {
        int m = cnt - bb; if (m > 8) m = 8;
        int   kid = 0;
        float dkl = 0.0f;
        if (lane < m) {
            kid = g_sorted[beg + bb + lane];
            dkl = (kid < O_NUM) ? g_dinv[kid] : RSQRT2F;
        }
        #pragma unroll
        for (int i = 0; i < 8; i++) {
            if (i >= m) break;
            int   k  = __shfl_sync(0xFFFFFFFFu, kid, i);
            float dk = __shfl_sync(0xFFFFFFFFu, dkl, i);
            const float4* xk = reinterpret_cast<const float4*>(row_ptr(k, obj, pred));
            float4 v = __ldg(xk + lane);
            acc.x = fmaf(v.x, dk, acc.x);
            acc.y = fmaf(v.y, dk, acc.y);
            acc.z = fmaf(v.z, dk, acc.z);
            acc.w = fmaf(v.w, dk, acc.w);
        }
    }

    acc.x *= dn; acc.y *= dn; acc.z *= dn; acc.w *= dn;

    float v4[4] = {acc.x, acc.y, acc.z, acc.w};
    alignas(8) __nv_bfloat16 h[4];
    alignas(8) __nv_bfloat16 l[4];
    #pragma unroll
    for (int i = 0; i < 4; i++) {
        h[i] = __float2bfloat16(v4[i]);
        l[i] = __float2bfloat16(v4[i] - __bfloat162float(h[i]));
    }
    size_t base = (size_t)n * D_DIM + lane * 4;
    *reinterpret_cast<uint2*>(g_yh + base) = *reinterpret_cast<const uint2*>(h);
    *reinterpret_cast<uint2*>(g_yl + base) = *reinterpret_cast<const uint2*>(l);
}

// ---------------- K8: out = Y @ W^T + b, 64-row tiles, 2 CTAs/SM ----------------
__device__ __forceinline__ void mma16816(float c[4], const uint32_t a[4], const uint32_t b[2]) {
    asm("mma.sync.aligned.m16n8k16.row.col.f32.bf16.bf16.f32 "
        "{%0,%1,%2,%3}, {%4,%5,%6,%7}, {%8,%9}, {%0,%1,%2,%3};"
        : "+f"(c[0]), "+f"(c[1]), "+f"(c[2]), "+f"(c[3])
        : "r"(a[0]), "r"(a[1]), "r"(a[2]), "r"(a[3]), "r"(b[0]), "r"(b[1]));
}

#define LDSY 136
#define SMEM_W_HALF (128 * LDSY)
#define SMEM_Y_HALF (64 * LDSY)
#define GEMM_SMEM_BYTES ((2 * SMEM_W_HALF + 2 * SMEM_Y_HALF) * 2)   // ~104.4 KB

__device__ __forceinline__ uint32_t lds32(const __nv_bfloat16* p) {
    return *reinterpret_cast<const uint32_t*>(p);
}

extern __shared__ char sm_raw[];

__global__ __launch_bounds__(256) void gemm_mma_kernel(const float* __restrict__ pred,
                                                       const float* __restrict__ bias,
                                                       float* __restrict__ out) {
    __nv_bfloat16* sWh = reinterpret_cast<__nv_bfloat16*>(sm_raw);
    __nv_bfloat16* sWl = sWh + SMEM_W_HALF;
    __nv_bfloat16* sYh = sWl + SMEM_W_HALF;
    __nv_bfloat16* sYl = sYh + SMEM_Y_HALF;

    int tid  = threadIdx.x;
    int warp = tid >> 5, lane = tid & 31;
    int g  = lane >> 2;
    int tg = lane & 3;
    int rowbase = blockIdx.x * 64;

    // stage W (both halves), coalesced uint4
    #pragma unroll
    for (int it = 0; it < 8; it++) {
        int r = it * 16 + (tid >> 4);
        int cseg = tid & 15;
        uint4 vh = *reinterpret_cast<const uint4*>(g_wh + r * D_DIM + cseg * 8);
        uint4 vl = *reinterpret_cast<const uint4*>(g_wl + r * D_DIM + cseg * 8);
        *reinterpret_cast<uint4*>(sWh + r * LDSY + cseg * 8) = vh;
        *reinterpret_cast<uint4*>(sWl + r * LDSY + cseg * 8) = vl;
    }

    if (rowbase >= T_NUM) {
        // identity rows: y = x (pred), split on the fly (deg = 1), float4 loads
        #pragma unroll
        for (int it = 0; it < 4; it++) {
            int r = it * 16 + (tid >> 4);
            int cseg = tid & 15;
            int grow = rowbase + r;
            alignas(16) __nv_bfloat16 h[8];
            alignas(16) __nv_bfloat16 l[8];
            if (grow < N_NUM) {
                const float4* src = reinterpret_cast<const float4*>(
                    pred + (size_t)(grow - O_NUM) * D_DIM + cseg * 8);
                float4 f0 = __ldg(src);
                float4 f1 = __ldg(src + 1);
                float ff[8] = {f0.x, f0.y, f0.z, f0.w, f1.x, f1.y, f1.z, f1.w};
                #pragma unroll
                for (int q = 0; q < 8; q++) {
                    h[q] = __float2bfloat16(ff[q]);
                    l[q] = __float2bfloat16(ff[q] - __bfloat162float(h[q]));
                }
            } else {
                #pragma unroll
                for (int q = 0; q < 8; q++) { h[q] = __float2bfloat16(0.f); l[q] = h[q]; }
            }
            *reinterpret_cast<uint4*>(sYh + r * LDSY + cseg * 8) = *reinterpret_cast<const uint4*>(h);
            *reinterpret_cast<uint4*>(sYl + r * LDSY + cseg * 8) = *reinterpret_cast<const uint4*>(l);
        }
    } else {
        #pragma unroll
        for (int it = 0; it < 4; it++) {
            int r = it * 16 + (tid >> 4);
            int cseg = tid & 15;
            int grow = rowbase + r;
            uint4 vh = *reinterpret_cast<const uint4*>(g_yh + (size_t)grow * D_DIM + cseg * 8);
            uint4 vl = *reinterpret_cast<const uint4*>(g_yl + (size_t)grow * D_DIM + cseg * 8);
            *reinterpret_cast<uint4*>(sYh + r * LDSY + cseg * 8) = vh;
            *reinterpret_cast<uint4*>(sYl + r * LDSY + cseg * 8) = vl;
        }
    }
    __syncthreads();

    int band = warp >> 1;
    int ch   = warp & 1;

    const __nv_bfloat16* aH0 = sYh + (band * 16 + g) * LDSY;
    const __nv_bfloat16* aL0 = sYl + (band * 16 + g) * LDSY;

    float c[8][4];
    #pragma unroll
    for (int n = 0; n < 8; n++)
        #pragma unroll
        for (int q = 0; q < 4; q++) c[n][q] = 0.0f;

    #pragma unroll
    for (int kt = 0; kt < 8; kt++) {
        int k = kt * 16;
        uint32_t ah[4], al[4];
        ah[0] = lds32(aH0 + k + tg * 2);
        ah[1] = lds32(aH0 + 8 * LDSY + k + tg * 2);
        ah[2] = lds32(aH0 + k + 8 + tg * 2);
        ah[3] = lds32(aH0 + 8 * LDSY + k + 8 + tg * 2);
        al[0] = lds32(aL0 + k + tg * 2);
        al[1] = lds32(aL0 + 8 * LDSY + k + tg * 2);
        al[2] = lds32(aL0 + k + 8 + tg * 2);
        al[3] = lds32(aL0 + 8 * LDSY + k + 8 + tg * 2);

        #pragma unroll
        for (int n = 0; n < 8; n++) {
            int cw = ch * 64 + n * 8 + g;
            const __nv_bfloat16* bH = sWh + cw * LDSY + k + tg * 2;
            const __nv_bfloat16* bL = sWl + cw * LDSY + k + tg * 2;
            uint32_t bh[2] = { lds32(bH), lds32(bH + 8) };
            uint32_t bl[2] = { lds32(bL), lds32(bL + 8) };
            mma16816(c[n], ah, bh);
            mma16816(c[n], al, bh);
            mma16816(c[n], ah, bl);
        }
    }

    int r0 = rowbase + band * 16 + g;
    int r1 = r0 + 8;
    #pragma unroll
    for (int n = 0; n < 8; n++) {
        int col = ch * 64 + n * 8 + tg * 2;
        float2 bb = *reinterpret_cast<const float2*>(bias + col);
        if (r0 < N_NUM) {
            float2 o = make_float2(c[n][0] + bb.x, c[n][1] + bb.y);
            *reinterpret_cast<float2*>(out + (size_t)r0 * D_DIM + col) = o;
        }
        if (r1 < N_NUM) {
            float2 o = make_float2(c[n][2] + bb.x, c[n][3] + bb.y);
            *reinterpret_cast<float2*>(out + (size_t)r1 * D_DIM + col) = o;
        }
    }
}

// ---------------- launch ----------------
extern "C" void kernel_launch(void* const* d_in, const int* in_sizes, int n_in,
                              void* d_out, int out_size) {
    const float* obj   = (const float*)d_in[0];
    const float* pred  = (const float*)d_in[1];
    const int*   e32   = (const int*)d_in[2];
    const float* W     = (const float*)d_in[3];
    const float* bias  = (const float*)d_in[4];
    float*       out   = (float*)d_out;

    cudaFuncSetAttribute(gemm_mma_kernel,
                         cudaFuncAttributeMaxDynamicSharedMemorySize, GEMM_SMEM_BYTES);

    prep_kernel<<<NPART + WBLK + 1, 256>>>(W, e32);                         // 1
    hist_kernel<<<(T_NUM + 255) / 256, 256>>>(e32);                         // 2
    scan_block_kernel<<<NPART, 256>>>();                                    // 3
    scan_fix_kernel<<<NPART, 256>>>();                                      // 4
    agg_easy_kernel<<<(T_NUM - O_NUM + 7) / 8, 256>>>(obj, pred, e32);      // 5
    csr_scatter_kernel<<<(T_NUM + 255) / 256, 256>>>(e32);                  // 6
    agg_hard_kernel<<<(O_NUM + 7) / 8, 256>>>(obj, pred, e32);              // 7
    gemm_mma_kernel<<<(N_NUM + 63) / 64, 256, GEMM_SMEM_BYTES>>>(pred, bias, out);  // 8
}

// round 10
// speedup vs baseline: 2.2035x; 1.0118x over previous
#include <cuda_runtime.h>
#include <cuda_bf16.h>
#include <cstdint>

#define O_NUM 50000
#define T_NUM 200000
#define N_NUM (O_NUM + T_NUM)
#define D_DIM 128
#define NPART 196           // ceil(O_NUM/256)
#define WBLK  64            // wconv blocks (16384/256)
#define RSQRT2F 0.7071067811865476f

// ---------------- scratch (no allocations allowed) ----------------
__device__ __nv_bfloat16 g_yh[(size_t)T_NUM * D_DIM];   // rows >= T_NUM handled from pred
__device__ __nv_bfloat16 g_yl[(size_t)T_NUM * D_DIM];
__device__ __nv_bfloat16 g_wh[D_DIM * D_DIM];
__device__ __nv_bfloat16 g_wl[D_DIM * D_DIM];
__device__ float     g_dinv[O_NUM];
__device__ int       g_counts[O_NUM];
__device__ int       g_offs[O_NUM + 1];
__device__ int       g_cursor[O_NUM];
__device__ int       g_sorted[T_NUM];
__device__ int       g_part[NPART];
__device__ int       g_stride;
__device__ int       g_doff;

__device__ __forceinline__ int edge_src(const int* e32, int t, int stride) {
    return __ldg(e32 + (size_t)stride * t);
}
__device__ __forceinline__ int edge_dst(const int* e32, int t, int stride, int doff) {
    return __ldg(e32 + (size_t)stride * t + doff);
}
__device__ __forceinline__ const float* row_ptr(int k, const float* obj, const float* pred) {
    return (k < O_NUM) ? (obj + (size_t)k * D_DIM) : (pred + (size_t)(k - O_NUM) * D_DIM);
}

// ---------------- K1: prep = zero counters + W split + dtype detect ----------------
__global__ void prep_kernel(const float* __restrict__ W, const int* __restrict__ e32) {
    int b = blockIdx.x;
    if (b < NPART) {
        int i = b * 256 + threadIdx.x;
        if (i < O_NUM) { g_counts[i] = 0; g_cursor[i] = 0; }
    } else if (b < NPART + WBLK) {
        int i = (b - NPART) * 256 + threadIdx.x;
        float w = W[i];
        __nv_bfloat16 h = __float2bfloat16(w);
        g_wh[i] = h;
        g_wl[i] = __float2bfloat16(w - __bfloat162float(h));
    } else {
        if (threadIdx.x < 32) {
            int acc = 0;
            for (int i = threadIdx.x; i < 4096; i += 32) acc |= e32[2 * i + 1];
            #pragma unroll
            for (int off = 16; off; off >>= 1) acc |= __shfl_xor_sync(0xFFFFFFFFu, acc, off);
            if (threadIdx.x == 0) {
                g_stride = acc ? 2 : 4;
                g_doff   = acc ? 1 : 2;
            }
        }
    }
}

// ---------------- K2: histogram of edges[:,1] ----------------
__global__ void hist_kernel(const int* __restrict__ e32) {
    int t = blockIdx.x * blockDim.x + threadIdx.x;
    if (t < T_NUM) {
        int d = edge_dst(e32, t, g_stride, g_doff);
        atomicAdd(&g_counts[d], 1);
    }
}

// ---------------- K3: per-block exclusive scan ----------------
__global__ __launch_bounds__(256) void scan_block_kernel() {
    int t = threadIdx.x;
    int i = blockIdx.x * 256 + t;
    int lane = t & 31, w = t >> 5;
    int v = (i < O_NUM) ? g_counts[i] : 0;

    int iv = v;
    #pragma unroll
    for (int off = 1; off < 32; off <<= 1) {
        int n = __shfl_up_sync(0xFFFFFFFFu, iv, off);
        if (lane >= off) iv += n;
    }
    __shared__ int ws[8];
    if (lane == 31) ws[w] = iv;
    __syncthreads();
    if (w == 0 && lane < 8) {
        int x = ws[lane];
        #pragma unroll
        for (int off = 1; off < 8; off <<= 1) {
            int n = __shfl_up_sync(0x000000FFu, x, off);
            if (lane >= off) x += n;
        }
        ws[lane] = x;
    }
    __syncthreads();
    int excl = iv - v + (w ? ws[w - 1] : 0);
    if (i < O_NUM) g_offs[i] = excl;
    if (t == 255) g_part[blockIdx.x] = excl + v;
}

// ---------------- K4: fixup (per-block prefix of partials) + dinv ----------------
__global__ __launch_bounds__(256) void scan_fix_kernel() {
    int b = blockIdx.x;
    int t = threadIdx.x;
    int lane = t & 31, w = t >> 5;

    int v = (t < b) ? g_part[t] : 0;
    #pragma unroll
    for (int off = 16; off; off >>= 1) v += __shfl_xor_sync(0xFFFFFFFFu, v, off);
    __shared__ int ws[8];
    if (lane == 0) ws[w] = v;
    __syncthreads();
    __shared__ int base_s;
    if (t == 0) {
        int s = 0;
        #pragma unroll
        for (int q = 0; q < 8; q++) s += ws[q];
        base_s = s;
    }
    __syncthreads();
    int base = base_s;

    int i = b * 256 + t;
    if (i < O_NUM) {
        g_offs[i] += base;
        g_dinv[i] = rsqrtf(2.0f + (float)g_counts[i]);
    }
    if (b == NPART - 1 && t == 0) g_offs[O_NUM] = base + g_part[NPART - 1];
}

// ---------------- K5: easy rows n in [O_NUM, T_NUM): self + one obj gather ----------------
__global__ __launch_bounds__(256) void agg_easy_kernel(const float* __restrict__ obj,
                                                       const float* __restrict__ pred,
                                                       const int* __restrict__ e32) {
    int gwarp = (blockIdx.x * blockDim.x + threadIdx.x) >> 5;
    int lane  = threadIdx.x & 31;
    if (gwarp >= T_NUM - O_NUM) return;
    int n = O_NUM + gwarp;                    // node index, pred row = gwarp

    const float4* xn = reinterpret_cast<const float4*>(pred + (size_t)gwarp * D_DIM);
    float4 a = __ldg(xn + lane);
    int s = edge_src(e32, n, g_stride);
    float ds = g_dinv[s];
    const float4* xs = reinterpret_cast<const float4*>(obj + (size_t)s * D_DIM);
    float4 v = __ldg(xs + lane);

    const float dn = RSQRT2F;
    float4 acc;
    acc.x = (fmaf(v.x, ds, a.x * dn)) * dn;
    acc.y = (fmaf(v.y, ds, a.y * dn)) * dn;
    acc.z = (fmaf(v.z, ds, a.z * dn)) * dn;
    acc.w = (fmaf(v.w, ds, a.w * dn)) * dn;

    float v4[4] = {acc.x, acc.y, acc.z, acc.w};
    alignas(8) __nv_bfloat16 h[4];
    alignas(8) __nv_bfloat16 l[4];
    #pragma unroll
    for (int q = 0; q < 4; q++) {
        h[q] = __float2bfloat16(v4[q]);
        l[q] = __float2bfloat16(v4[q] - __bfloat162float(h[q]));
    }
    size_t base = (size_t)n * D_DIM + lane * 4;
    *reinterpret_cast<uint2*>(g_yh + base) = *reinterpret_cast<const uint2*>(h);
    *reinterpret_cast<uint2*>(g_yl + base) = *reinterpret_cast<const uint2*>(l);
}

// ---------------- K6: counting-sort scatter ----------------
__global__ void csr_scatter_kernel(const int* __restrict__ e32) {
    int t = blockIdx.x * blockDim.x + threadIdx.x;
    if (t < T_NUM) {
        int d = edge_dst(e32, t, g_stride, g_doff);
        int pos = g_offs[d] + atomicAdd(&g_cursor[d], 1);
        g_sorted[pos] = t;
    }
}

// ---------------- K7: hard rows n < O_NUM: self + obj gather + bucket ----------------
__global__ __launch_bounds__(256) void agg_hard_kernel(const float* __restrict__ obj,
                                                       const float* __restrict__ pred,
                                                       const int* __restrict__ e32) {
    int n = (blockIdx.x * blockDim.x + threadIdx.x) >> 5;
    int lane  = threadIdx.x & 31;
    if (n >= O_NUM) return;
    float dn = g_dinv[n];

    const float4* xn = reinterpret_cast<const float4*>(obj + (size_t)n * D_DIM);
    float4 a = __ldg(xn + lane);

    int s = edge_src(e32, n, g_stride);
    float ds = g_dinv[s];
    const float4* xs = reinterpret_cast<const float4*>(obj + (size_t)s * D_DIM);
    float4 v1 = __ldg(xs + lane);

    float4 acc;
    acc.x = fmaf(v1.x, ds, a.x * dn);
    acc.y = fmaf(v1.y, ds, a.y * dn);
    acc.z = fmaf(v1.z, ds, a.z * dn);
    acc.w = fmaf(v1.w, ds, a.w * dn);

    int beg = g_offs[n];
    int cnt = g_offs[n + 1] - beg;
    for (int bb = 0; bb < cnt; bb += 8) {
        int m = cnt - bb; if (m > 8) m = 8;
        int   kid = 0;
        float dkl = 0.0f;
        if (lane < m) {
            kid = g_sorted[beg + bb + lane];
            dkl = (kid < O_NUM) ? g_dinv[kid] : RSQRT2F;
        }
        #pragma unroll
        for (int i = 0; i < 8; i++) {
            if (i >= m) break;
            int   k  = __shfl_sync(0xFFFFFFFFu, kid, i);
            float dk = __shfl_sync(0xFFFFFFFFu, dkl, i);
            const float4* xk = reinterpret_cast<const float4*>(row_ptr(k, obj, pred));
            float4 v = __ldg(xk + lane);
            acc.x = fmaf(v.x, dk, acc.x);
            acc.y = fmaf(v.y, dk, acc.y);
            acc.z = fmaf(v.z, dk, acc.z);
            acc.w = fmaf(v.w, dk, acc.w);
        }
    }

    acc.x *= dn; acc.y *= dn; acc.z *= dn; acc.w *= dn;

    float v4[4] = {acc.x, acc.y, acc.z, acc.w};
    alignas(8) __nv_bfloat16 h[4];
    alignas(8) __nv_bfloat16 l[4];
    #pragma unroll
    for (int i = 0; i < 4; i++) {
        h[i] = __float2bfloat16(v4[i]);
        l[i] = __float2bfloat16(v4[i] - __bfloat162float(h[i]));
    }
    size_t base = (size_t)n * D_DIM + lane * 4;
    *reinterpret_cast<uint2*>(g_yh + base) = *reinterpret_cast<const uint2*>(h);
    *reinterpret_cast<uint2*>(g_yl + base) = *reinterpret_cast<const uint2*>(l);
}

// ---------------- K8: persistent double-buffered GEMM ----------------
__device__ __forceinline__ void mma16816(float c[4], const uint32_t a[4], const uint32_t b[2]) {
    asm("mma.sync.aligned.m16n8k16.row.col.f32.bf16.bf16.f32 "
        "{%0,%1,%2,%3}, {%4,%5,%6,%7}, {%8,%9}, {%0,%1,%2,%3};"
        : "+f"(c[0]), "+f"(c[1]), "+f"(c[2]), "+f"(c[3])
        : "r"(a[0]), "r"(a[1]), "r"(a[2]), "r"(a[3]), "r"(b[0]), "r"(b[1]));
}

#define LDSY 136
#define TILE_M 32
#define SMEM_W_HALF (128 * LDSY)
#define SMEM_Y_HALF (TILE_M * LDSY)
// W(hi,lo) + 2 x Y-buffer(hi,lo)
#define GEMM_SMEM_BYTES ((2 * SMEM_W_HALF + 4 * SMEM_Y_HALF) * 2)   // 104448 B

#define NT_N (T_NUM / TILE_M)                      // 6250 normal tiles
#define NT_I ((N_NUM - T_NUM + TILE_M - 1) / TILE_M)  // 1563 identity tiles
#define CTA_N 237
#define CTA_I 59
#define GRID_GEMM (CTA_N + CTA_I)                  // 296 = 2 per SM

__device__ __forceinline__ uint32_t lds32(const __nv_bfloat16* p) {
    return *reinterpret_cast<const uint32_t*>(p);
}
__device__ __forceinline__ void cp_async16(uint32_t dst, const void* src) {
    asm volatile("cp.async.cg.shared.global [%0], [%1], 16;" :: "r"(dst), "l"(src));
}
#define CP_COMMIT() asm volatile("cp.async.commit_group;" ::: "memory")
#define CP_WAIT1()  asm volatile("cp.async.wait_group 1;" ::: "memory")

extern __shared__ char sm_raw[];

__global__ __launch_bounds__(256) void gemm_persist_kernel(const float* __restrict__ pred,
                                                           const float* __restrict__ bias,
                                                           float* __restrict__ out) {
    __nv_bfloat16* sWh = reinterpret_cast<__nv_bfloat16*>(sm_raw);
    __nv_bfloat16* sWl = sWh + SMEM_W_HALF;
    __nv_bfloat16* sY  = sWl + SMEM_W_HALF;   // 2 bufs x (hi, lo)

    int tid  = threadIdx.x;
    int warp = tid >> 5, lane = tid & 31;
    int g  = lane >> 2;
    int tg = lane & 3;
    int band = warp >> 2;   // 0..1 -> 16 rows
    int colq = warp & 3;    // 0..3 -> 32 cols

    // stage W once
    #pragma unroll
    for (int it = 0; it < 8; it++) {
        int r = it * 16 + (tid >> 4);
        int cseg = tid & 15;
        uint4 vh = *reinterpret_cast<const uint4*>(g_wh + r * D_DIM + cseg * 8);
        uint4 vl = *reinterpret_cast<const uint4*>(g_wl + r * D_DIM + cseg * 8);
        *reinterpret_cast<uint4*>(sWh + r * LDSY + cseg * 8) = vh;
        *reinterpret_cast<uint4*>(sWl + r * LDSY + cseg * 8) = vl;
    }

    // --- tile MMA + store (shared by both partitions) ---
    auto mma_store = [&](int rowbase, const __nv_bfloat16* bYh, const __nv_bfloat16* bYl,
                         bool guard) {
        const __nv_bfloat16* aH0 = bYh + (band * 16 + g) * LDSY;
        const __nv_bfloat16* aL0 = bYl + (band * 16 + g) * LDSY;

        float c[4][4];
        #pragma unroll
        for (int n = 0; n < 4; n++)
            #pragma unroll
            for (int q = 0; q < 4; q++) c[n][q] = 0.0f;

        #pragma unroll
        for (int kt = 0; kt < 8; kt++) {
            int k = kt * 16;
            uint32_t ah[4], al[4];
            ah[0] = lds32(aH0 + k + tg * 2);
            ah[1] = lds32(aH0 + 8 * LDSY + k + tg * 2);
            ah[2] = lds32(aH0 + k + 8 + tg * 2);
            ah[3] = lds32(aH0 + 8 * LDSY + k + 8 + tg * 2);
            al[0] = lds32(aL0 + k + tg * 2);
            al[1] = lds32(aL0 + 8 * LDSY + k + tg * 2);
            al[2] = lds32(aL0 + k + 8 + tg * 2);
            al[3] = lds32(aL0 + 8 * LDSY + k + 8 + tg * 2);

            #pragma unroll
            for (int n = 0; n < 4; n++) {
                int cw = colq * 32 + n * 8 + g;
                const __nv_bfloat16* bH = sWh + cw * LDSY + k + tg * 2;
                const __nv_bfloat16* bL = sWl + cw * LDSY + k + tg * 2;
                uint32_t bh[2] = { lds32(bH), lds32(bH + 8) };
                uint32_t bl[2] = { lds32(bL), lds32(bL + 8) };
                mma16816(c[n], ah, bh);
                mma16816(c[n], al, bh);
                mma16816(c[n], ah, bl);
            }
        }

        int r0 = rowbase + band * 16 + g;
        int r1 = r0 + 8;
        #pragma unroll
        for (int n = 0; n < 4; n++) {
            int col = colq * 32 + n * 8 + tg * 2;
            float2 bb = *reinterpret_cast<const float2*>(bias + col);
            if (!guard || r0 < N_NUM) {
                float2 o = make_float2(c[n][0] + bb.x, c[n][1] + bb.y);
                *reinterpret_cast<float2*>(out + (size_t)r0 * D_DIM + col) = o;
            }
            if (!guard || r1 < N_NUM) {
                float2 o = make_float2(c[n][2] + bb.x, c[n][3] + bb.y);
                *reinterpret_cast<float2*>(out + (size_t)r1 * D_DIM + col) = o;
            }
        }
    };

    if (blockIdx.x < CTA_N) {
        // ---------- normal tiles: cp.async double-buffered ----------
        uint32_t sY_base = (uint32_t)__cvta_generic_to_shared(sY);

        auto load_async = [&](int tile, int buf) {
            int rowbase = tile * TILE_M;
            #pragma unroll
            for (int q = 0; q < 4; q++) {
                int c = tid + q * 256;          // 0..1023
                int half = c >> 9;              // 0: hi, 1: lo
                int r    = (c >> 4) & 31;
                int seg  = c & 15;
                const __nv_bfloat16* src = (half ? g_yl : g_yh)
                                         + (size_t)(rowbase + r) * D_DIM + seg * 8;
                uint32_t dst = sY_base
                             + ((buf * 2 + half) * SMEM_Y_HALF + r * LDSY + seg * 8) * 2;
                cp_async16(dst, src);
            }
        };

        int t0 = blockIdx.x;
        load_async(t0, 0);
        CP_COMMIT();
        int buf = 0;
        for (int t = t0; t < NT_N; t += CTA_N) {
            int tn = t + CTA_N;
            if (tn < NT_N) load_async(tn, buf ^ 1);
            CP_COMMIT();
            CP_WAIT1();
            __syncthreads();
            mma_store(t * TILE_M,
                      sY + (buf * 2 + 0) * SMEM_Y_HALF,
                      sY + (buf * 2 + 1) * SMEM_Y_HALF, false);
            buf ^= 1;
            __syncthreads();
        }
    } else {
        // ---------- identity tiles: synchronous fp32 split from pred ----------
        __nv_bfloat16* bYh = sY;                     // buf 0 hi
        __nv_bfloat16* bYl = sY + SMEM_Y_HALF;       // buf 0 lo
        int idx = blockIdx.x - CTA_N;
        for (int t = idx; t < NT_I; t += CTA_I) {
            int rowbase = T_NUM + t * TILE_M;
            __syncthreads();   // prior tile's reads done before overwrite
            #pragma unroll
            for (int q = 0; q < 2; q++) {
                int c = tid + q * 256;      // 0..511 chunks of 8 elems
                int r = c >> 4;
                int seg = c & 15;
                int grow = rowbase + r;
                alignas(16) __nv_bfloat16 h[8];
                alignas(16) __nv_bfloat16 l[8];
                if (grow < N_NUM) {
                    const float4* src = reinterpret_cast<const float4*>(
                        pred + (size_t)(grow - O_NUM) * D_DIM + seg * 8);
                    float4 f0 = __ldg(src);
                    float4 f1 = __ldg(src + 1);
                    float ff[8] = {f0.x, f0.y, f0.z, f0.w, f1.x, f1.y, f1.z, f1.w};
                    #pragma unroll
                    for (int p = 0; p < 8; p++) {
                        h[p] = __float2bfloat16(ff[p]);
                        l[p] = __float2bfloat16(ff[p] - __bfloat162float(h[p]));
                    }
                } else {
                    #pragma unroll
                    for (int p = 0; p < 8; p++) { h[p] = __float2bfloat16(0.f); l[p] = h[p]; }
                }
                *reinterpret_cast<uint4*>(bYh + r * LDSY + seg * 8) = *reinterpret_cast<const uint4*>(h);
                *reinterpret_cast<uint4*>(bYl + r * LDSY + seg * 8) = *reinterpret_cast<const uint4*>(l);
            }
            __syncthreads();
            mma_store(rowbase, bYh, bYl, true);
        }
    }
}

// ---------------- launch ----------------
extern "C" void kernel_launch(void* const* d_in, const int* in_sizes, int n_in,
                              void* d_out, int out_size) {
    const float* obj   = (const float*)d_in[0];
    const float* pred  = (const float*)d_in[1];
    const int*   e32   = (const int*)d_in[2];
    const float* W     = (const float*)d_in[3];
    const float* bias  = (const float*)d_in[4];
    float*       out   = (float*)d_out;

    cudaFuncSetAttribute(gemm_persist_kernel,
                         cudaFuncAttributeMaxDynamicSharedMemorySize, GEMM_SMEM_BYTES);

    prep_kernel<<<NPART + WBLK + 1, 256>>>(W, e32);                         // 1
    hist_kernel<<<(T_NUM + 255) / 256, 256>>>(e32);                         // 2
    scan_block_kernel<<<NPART, 256>>>();                                    // 3
    scan_fix_kernel<<<NPART, 256>>>();                                      // 4
    agg_easy_kernel<<<(T_NUM - O_NUM + 7) / 8, 256>>>(obj, pred, e32);      // 5
    csr_scatter_kernel<<<(T_NUM + 255) / 256, 256>>>(e32);                  // 6
    agg_hard_kernel<<<(O_NUM + 7) / 8, 256>>>(obj, pred, e32);              // 7
    gemm_persist_kernel<<<GRID_GEMM, 256, GEMM_SMEM_BYTES>>>(pred, bias, out);  // 8
}

// round 12
// speedup vs baseline: 2.6386x; 1.1974x over previous
#include <cuda_runtime.h>
#include <cuda_bf16.h>
#include <cstdint>

#define O_NUM 50000
#define T_NUM 200000
#define N_NUM (O_NUM + T_NUM)
#define D_DIM 128
#define NPART 196
#define WBLK  64
#define RSQRT2F 0.7071067811865476f

// ---------------- scratch ----------------
__device__ __nv_bfloat16 g_yh[(size_t)T_NUM * D_DIM];
__device__ __nv_bfloat16 g_yl[(size_t)T_NUM * D_DIM];
__device__ __nv_bfloat16 g_wh[D_DIM * D_DIM];
__device__ __nv_bfloat16 g_wl[D_DIM * D_DIM];
__device__ float     g_dinv[O_NUM];
__device__ int       g_counts[O_NUM];
__device__ int       g_offs[O_NUM + 1];
__device__ int       g_cursor[O_NUM];
__device__ int       g_sorted[T_NUM];
__device__ int       g_part[NPART];
__device__ int       g_stride;
__device__ int       g_doff;

__device__ __forceinline__ int edge_src(const int* e32, int t, int stride) {
    return __ldg(e32 + (size_t)stride * t);
}
__device__ __forceinline__ int edge_dst(const int* e32, int t, int stride, int doff) {
    return __ldg(e32 + (size_t)stride * t + doff);
}
__device__ __forceinline__ const float* row_ptr(int k, const float* obj, const float* pred) {
    return (k < O_NUM) ? (obj + (size_t)k * D_DIM) : (pred + (size_t)(k - O_NUM) * D_DIM);
}

// ---------------- K1: prep = zero counters + W split + dtype detect ----------------
__global__ void prep_kernel(const float* __restrict__ W, const int* __restrict__ e32) {
    int b = blockIdx.x;
    if (b < NPART) {
        int i = b * 256 + threadIdx.x;
        if (i < O_NUM) { g_counts[i] = 0; g_cursor[i] = 0; }
    } else if (b < NPART + WBLK) {
        int i = (b - NPART) * 256 + threadIdx.x;
        float w = W[i];
        __nv_bfloat16 h = __float2bfloat16(w);
        g_wh[i] = h;
        g_wl[i] = __float2bfloat16(w - __bfloat162float(h));
    } else {
        if (threadIdx.x < 32) {
            int acc = 0;
            for (int i = threadIdx.x; i < 4096; i += 32) acc |= e32[2 * i + 1];
            #pragma unroll
            for (int off = 16; off; off >>= 1) acc |= __shfl_xor_sync(0xFFFFFFFFu, acc, off);
            if (threadIdx.x == 0) {
                g_stride = acc ? 2 : 4;
                g_doff   = acc ? 1 : 2;
            }
        }
    }
}

// ---------------- K2: histogram ----------------
__global__ void hist_kernel(const int* __restrict__ e32) {
    int t = blockIdx.x * blockDim.x + threadIdx.x;
    if (t < T_NUM) {
        int d = edge_dst(e32, t, g_stride, g_doff);
        atomicAdd(&g_counts[d], 1);
    }
}

// ---------------- K3: per-block exclusive scan ----------------
__global__ __launch_bounds__(256) void scan_block_kernel() {
    int t = threadIdx.x;
    int i = blockIdx.x * 256 + t;
    int lane = t & 31, w = t >> 5;
    int v = (i < O_NUM) ? g_counts[i] : 0;

    int iv = v;
    #pragma unroll
    for (int off = 1; off < 32; off <<= 1) {
        int n = __shfl_up_sync(0xFFFFFFFFu, iv, off);
        if (lane >= off) iv += n;
    }
    __shared__ int ws[8];
    if (lane == 31) ws[w] = iv;
    __syncthreads();
    if (w == 0 && lane < 8) {
        int x = ws[lane];
        #pragma unroll
        for (int off = 1; off < 8; off <<= 1) {
            int n = __shfl_up_sync(0x000000FFu, x, off);
            if (lane >= off) x += n;
        }
        ws[lane] = x;
    }
    __syncthreads();
    int excl = iv - v + (w ? ws[w - 1] : 0);
    if (i < O_NUM) g_offs[i] = excl;
    if (t == 255) g_part[blockIdx.x] = excl + v;
}

// ---------------- K4: fixup + dinv ----------------
__global__ __launch_bounds__(256) void scan_fix_kernel() {
    int b = blockIdx.x;
    int t = threadIdx.x;
    int lane = t & 31, w = t >> 5;

    int v = (t < b) ? g_part[t] : 0;
    #pragma unroll
    for (int off = 16; off; off >>= 1) v += __shfl_xor_sync(0xFFFFFFFFu, v, off);
    __shared__ int ws[8];
    if (lane == 0) ws[w] = v;
    __syncthreads();
    __shared__ int base_s;
    if (t == 0) {
        int s = 0;
        #pragma unroll
        for (int q = 0; q < 8; q++) s += ws[q];
        base_s = s;
    }
    __syncthreads();
    int base = base_s;

    int i = b * 256 + t;
    if (i < O_NUM) {
        g_offs[i] += base;
        g_dinv[i] = rsqrtf(2.0f + (float)g_counts[i]);
    }
    if (b == NPART - 1 && t == 0) g_offs[O_NUM] = base + g_part[NPART - 1];
}

// ---------------- K5: easy rows ----------------
__global__ __launch_bounds__(256) void agg_easy_kernel(const float* __restrict__ obj,
                                                       const float* __restrict__ pred,
                                                       const int* __restrict__ e32) {
    int gwarp = (blockIdx.x * blockDim.x + threadIdx.x) >> 5;
    int lane  = threadIdx.x & 31;
    if (gwarp >= T_NUM - O_NUM) return;
    int n = O_NUM + gwarp;

    const float4* xn = reinterpret_cast<const float4*>(pred + (size_t)gwarp * D_DIM);
    float4 a = __ldg(xn + lane);
    int s = edge_src(e32, n, g_stride);
    float ds = g_dinv[s];
    const float4* xs = reinterpret_cast<const float4*>(obj + (size_t)s * D_DIM);
    float4 v = __ldg(xs + lane);

    const float dn = RSQRT2F;
    float4 acc;
    acc.x = (fmaf(v.x, ds, a.x * dn)) * dn;
    acc.y = (fmaf(v.y, ds, a.y * dn)) * dn;
    acc.z = (fmaf(v.z, ds, a.z * dn)) * dn;
    acc.w = (fmaf(v.w, ds, a.w * dn)) * dn;

    float v4[4] = {acc.x, acc.y, acc.z, acc.w};
    alignas(8) __nv_bfloat16 h[4];
    alignas(8) __nv_bfloat16 l[4];
    #pragma unroll
    for (int q = 0; q < 4; q++) {
        h[q] = __float2bfloat16(v4[q]);
        l[q] = __float2bfloat16(v4[q] - __bfloat162float(h[q]));
    }
    size_t base = (size_t)n * D_DIM + lane * 4;
    *reinterpret_cast<uint2*>(g_yh + base) = *reinterpret_cast<const uint2*>(h);
    *reinterpret_cast<uint2*>(g_yl + base) = *reinterpret_cast<const uint2*>(l);
}

// ---------------- K6: counting-sort scatter ----------------
__global__ void csr_scatter_kernel(const int* __restrict__ e32) {
    int t = blockIdx.x * blockDim.x + threadIdx.x;
    if (t < T_NUM) {
        int d = edge_dst(e32, t, g_stride, g_doff);
        int pos = g_offs[d] + atomicAdd(&g_cursor[d], 1);
        g_sorted[pos] = t;
    }
}

// ---------------- K7: hard rows ----------------
__global__ __launch_bounds__(256) void agg_hard_kernel(const float* __restrict__ obj,
                                                       const float* __restrict__ pred,
                                                       const int* __restrict__ e32) {
    int n = (blockIdx.x * blockDim.x + threadIdx.x) >> 5;
    int lane  = threadIdx.x & 31;
    if (n >= O_NUM) return;
    float dn = g_dinv[n];

    const float4* xn = reinterpret_cast<const float4*>(obj + (size_t)n * D_DIM);
    float4 a = __ldg(xn + lane);

    int s = edge_src(e32, n, g_stride);
    float ds = g_dinv[s];
    const float4* xs = reinterpret_cast<const float4*>(obj + (size_t)s * D_DIM);
    float4 v1 = __ldg(xs + lane);

    float4 acc;
    acc.x = fmaf(v1.x, ds, a.x * dn);
    acc.y = fmaf(v1.y, ds, a.y * dn);
    acc.z = fmaf(v1.z, ds, a.z * dn);
    acc.w = fmaf(v1.w, ds, a.w * dn);

    int beg = g_offs[n];
    int cnt = g_offs[n + 1] - beg;
    for (int bb = 0; bb < cnt; bb += 8) {
        int m = cnt - bb; if (m > 8) m = 8;
        int   kid = 0;
        float dkl = 0.0f;
        if (lane < m) {
            kid = g_sorted[beg + bb + lane];
            dkl = (kid < O_NUM) ? g_dinv[kid] : RSQRT2F;
        }
        #pragma unroll
        for (int i = 0; i < 8; i++) {
            if (i >= m) break;
            int   k  = __shfl_sync(0xFFFFFFFFu, kid, i);
            float dk = __shfl_sync(0xFFFFFFFFu, dkl, i);
            const float4* xk = reinterpret_cast<const float4*>(row_ptr(k, obj, pred));
            float4 v = __ldg(xk + lane);
            acc.x = fmaf(v.x, dk, acc.x);
            acc.y = fmaf(v.y, dk, acc.y);
            acc.z = fmaf(v.z, dk, acc.z);
            acc.w = fmaf(v.w, dk, acc.w);
        }
    }

    acc.x *= dn; acc.y *= dn; acc.z *= dn; acc.w *= dn;

    float v4[4] = {acc.x, acc.y, acc.z, acc.w};
    alignas(8) __nv_bfloat16 h[4];
    alignas(8) __nv_bfloat16 l[4];
    #pragma unroll
    for (int i = 0; i < 4; i++) {
        h[i] = __float2bfloat16(v4[i]);
        l[i] = __float2bfloat16(v4[i] - __bfloat162float(h[i]));
    }
    size_t base = (size_t)n * D_DIM + lane * 4;
    *reinterpret_cast<uint2*>(g_yh + base) = *reinterpret_cast<const uint2*>(h);
    *reinterpret_cast<uint2*>(g_yl + base) = *reinterpret_cast<const uint2*>(l);
}

// ============ K8: persistent GEMM, W cached in registers ============
__device__ __forceinline__ void mma16816(float c[4], const uint32_t a[4], const uint32_t b[2]) {
    asm("mma.sync.aligned.m16n8k16.row.col.f32.bf16.bf16.f32 "
        "{%0,%1,%2,%3}, {%4,%5,%6,%7}, {%8,%9}, {%0,%1,%2,%3};"
        : "+f"(c[0]), "+f"(c[1]), "+f"(c[2]), "+f"(c[3])
        : "r"(a[0]), "r"(a[1]), "r"(a[2]), "r"(a[3]), "r"(b[0]), "r"(b[1]));
}

#define LDSY 136
#define TILE_M 32
#define SMEM_W_HALF (128 * LDSY)
#define SMEM_A_HALF (TILE_M * LDSY)
#define GEMM_SMEM_BYTES ((2 * SMEM_W_HALF + 4 * SMEM_A_HALF) * 2)   // 104448 B

#define NT_TILES ((N_NUM + TILE_M - 1) / TILE_M)    // 7813
#define GEMM_GRID 148

__device__ __forceinline__ uint32_t lds32(const __nv_bfloat16* p) {
    return *reinterpret_cast<const uint32_t*>(p);
}
__device__ __forceinline__ void cp_async16(uint32_t dst, const void* src) {
    asm volatile("cp.async.cg.shared.global [%0], [%1], 16;" :: "r"(dst), "l"(src));
}
#define CP_COMMIT() asm volatile("cp.async.commit_group;" ::: "memory")
#define CP_WAIT1()  asm volatile("cp.async.wait_group 1;" ::: "memory")

extern __shared__ char sm_raw[];

__global__ __launch_bounds__(512, 1) void gemm_wreg_kernel(const float* __restrict__ pred,
                                                           const float* __restrict__ bias,
                                                           float* __restrict__ out) {
    __nv_bfloat16* sWh = reinterpret_cast<__nv_bfloat16*>(sm_raw);
    __nv_bfloat16* sWl = sWh + SMEM_W_HALF;
    __nv_bfloat16* sA  = sWl + SMEM_W_HALF;   // 2 bufs x (hi, lo), each TILE_M*LDSY

    int tid  = threadIdx.x;
    int warp = tid >> 5, lane = tid & 31;
    int g  = lane >> 2;
    int tg = lane & 3;
    int band = warp >> 3;   // 0..1 -> rows band*16..
    int cg   = warp & 7;    // 0..7 -> cols cg*16..

    // ---- stage W (hi+lo) into smem: 4096 x 16B chunks ----
    #pragma unroll
    for (int it = 0; it < 8; it++) {
        int idx = tid + it * 512;           // 0..4095
        int half = idx >> 11;
        int r    = (idx >> 4) & 127;
        int seg  = idx & 15;
        const __nv_bfloat16* src = (half ? g_wl : g_wh) + r * D_DIM + seg * 8;
        __nv_bfloat16* dst = (half ? sWl : sWh) + r * LDSY + seg * 8;
        *reinterpret_cast<uint4*>(dst) = *reinterpret_cast<const uint4*>(src);
    }
    __syncthreads();

    // ---- load this warp's W fragments into registers (64 regs) ----
    uint32_t wfh[8][2][2], wfl[8][2][2];
    #pragma unroll
    for (int kt = 0; kt < 8; kt++) {
        #pragma unroll
        for (int n = 0; n < 2; n++) {
            int cw = cg * 16 + n * 8 + g;
            const __nv_bfloat16* pH = sWh + cw * LDSY + kt * 16 + tg * 2;
            const __nv_bfloat16* pL = sWl + cw * LDSY + kt * 16 + tg * 2;
            wfh[kt][n][0] = lds32(pH); wfh[kt][n][1] = lds32(pH + 8);
            wfl[kt][n][0] = lds32(pL); wfl[kt][n][1] = lds32(pL + 8);
        }
    }

    // bias for this warp's columns
    float2 bb[2];
    #pragma unroll
    for (int n = 0; n < 2; n++)
        bb[n] = __ldg(reinterpret_cast<const float2*>(bias + cg * 16 + n * 8 + tg * 2));

    uint32_t sA_u32 = (uint32_t)__cvta_generic_to_shared(sA);

    // ---- stage one A tile (32 rows, hi+lo = 1024 x 16B chunks) ----
    auto stage = [&](int tile, int buf) {
        int rowbase = tile * TILE_M;
        #pragma unroll
        for (int q = 0; q < 2; q++) {
            int idx = tid + q * 512;         // 0..1023
            int half = idx >> 9;
            int r    = (idx >> 4) & 31;
            int seg  = idx & 15;
            int grow = rowbase + r;
            uint32_t off = ((buf * 2 + half) * SMEM_A_HALF + r * LDSY + seg * 8) * 2;
            if (grow < T_NUM) {
                const __nv_bfloat16* src = (half ? g_yl : g_yh) + (size_t)grow * D_DIM + seg * 8;
                cp_async16(sA_u32 + off, src);
            } else {
                alignas(16) __nv_bfloat16 v[8];
                if (grow < N_NUM) {
                    const float4* s = reinterpret_cast<const float4*>(
                        pred + (size_t)(grow - O_NUM) * D_DIM + seg * 8);
                    float4 f0 = __ldg(s), f1 = __ldg(s + 1);
                    float ff[8] = {f0.x, f0.y, f0.z, f0.w, f1.x, f1.y, f1.z, f1.w};
                    #pragma unroll
                    for (int p = 0; p < 8; p++) {
                        __nv_bfloat16 hh = __float2bfloat16(ff[p]);
                        v[p] = half ? __float2bfloat16(ff[p] - __bfloat162float(hh)) : hh;
                    }
                } else {
                    #pragma unroll
                    for (int p = 0; p < 8; p++) v[p] = __float2bfloat16(0.f);
                }
                *reinterpret_cast<uint4*>(reinterpret_cast<char*>(sA) + off) =
                    *reinterpret_cast<const uint4*>(v);
            }
        }
    };

    int t0 = blockIdx.x;
    if (t0 < NT_TILES) stage(t0, 0);
    CP_COMMIT();

    int buf = 0;
    for (int t = t0; t < NT_TILES; t += GEMM_GRID) {
        int tn = t + GEMM_GRID;
        if (tn < NT_TILES) stage(tn, buf ^ 1);
        CP_COMMIT();
        CP_WAIT1();
        __syncthreads();

        const __nv_bfloat16* bAh = sA + (buf * 2 + 0) * SMEM_A_HALF;
        const __nv_bfloat16* bAl = sA + (buf * 2 + 1) * SMEM_A_HALF;
        const __nv_bfloat16* aH0 = bAh + (band * 16 + g) * LDSY;
        const __nv_bfloat16* aL0 = bAl + (band * 16 + g) * LDSY;

        float c[2][4];
        #pragma unroll
        for (int n = 0; n < 2; n++)
            #pragma unroll
            for (int q = 0; q < 4; q++) c[n][q] = 0.0f;

        #pragma unroll
        for (int kt = 0; kt < 8; kt++) {
            int k = kt * 16;
            uint32_t ah[4], al[4];
            ah[0] = lds32(aH0 + k + tg * 2);
            ah[1] = lds32(aH0 + 8 * LDSY + k + tg * 2);
            ah[2] = lds32(aH0 + k + 8 + tg * 2);
            ah[3] = lds32(aH0 + 8 * LDSY + k + 8 + tg * 2);
            al[0] = lds32(aL0 + k + tg * 2);
            al[1] = lds32(aL0 + 8 * LDSY + k + tg * 2);
            al[2] = lds32(aL0 + k + 8 + tg * 2);
            al[3] = lds32(aL0 + 8 * LDSY + k + 8 + tg * 2);

            #pragma unroll
            for (int n = 0; n < 2; n++) {
                mma16816(c[n], ah, wfh[kt][n]);
                mma16816(c[n], al, wfh[kt][n]);
                mma16816(c[n], ah, wfl[kt][n]);
            }
        }

        int rowbase = t * TILE_M;
        int r0 = rowbase + band * 16 + g;
        int r1 = r0 + 8;
        #pragma unroll
        for (int n = 0; n < 2; n++) {
            int col = cg * 16 + n * 8 + tg * 2;
            if (r0 < N_NUM) {
                float2 o = make_float2(c[n][0] + bb[n].x, c[n][1] + bb[n].y);
                *reinterpret_cast<float2*>(out + (size_t)r0 * D_DIM + col) = o;
            }
            if (r1 < N_NUM) {
                float2 o = make_float2(c[n][2] + bb[n].x, c[n][3] + bb[n].y);
                *reinterpret_cast<float2*>(out + (size_t)r1 * D_DIM + col) = o;
            }
        }
        buf ^= 1;
        __syncthreads();
    }
}

// ---------------- launch ----------------
extern "C" void kernel_launch(void* const* d_in, const int* in_sizes, int n_in,
                              void* d_out, int out_size) {
    const float* obj   = (const float*)d_in[0];
    const float* pred  = (const float*)d_in[1];
    const int*   e32   = (const int*)d_in[2];
    const float* W     = (const float*)d_in[3];
    const float* bias  = (const float*)d_in[4];
    float*       out   = (float*)d_out;

    cudaFuncSetAttribute(gemm_wreg_kernel,
                         cudaFuncAttributeMaxDynamicSharedMemorySize, GEMM_SMEM_BYTES);

    prep_kernel<<<NPART + WBLK + 1, 256>>>(W, e32);                         // 1
    hist_kernel<<<(T_NUM + 255) / 256, 256>>>(e32);                         // 2
    scan_block_kernel<<<NPART, 256>>>();                                    // 3
    scan_fix_kernel<<<NPART, 256>>>();                                      // 4
    agg_easy_kernel<<<(T_NUM - O_NUM + 7) / 8, 256>>>(obj, pred, e32);      // 5
    csr_scatter_kernel<<<(T_NUM + 255) / 256, 256>>>(e32);                  // 6
    agg_hard_kernel<<<(O_NUM + 7) / 8, 256>>>(obj, pred, e32);              // 7
    gemm_wreg_kernel<<<GEMM_GRID, 512, GEMM_SMEM_BYTES>>>(pred, bias, out); // 8
}

// round 13
// speedup vs baseline: 2.7063x; 1.0257x over previous
#include <cuda_runtime.h>
#include <cuda_bf16.h>
#include <cstdint>

#define O_NUM 50000
#define T_NUM 200000
#define N_NUM (O_NUM + T_NUM)
#define D_DIM 128
#define NPART 196
#define WBLK  64
#define RSQRT2F 0.7071067811865476f

// ---------------- scratch ----------------
__device__ __nv_bfloat16 g_yh[(size_t)T_NUM * D_DIM];
__device__ __nv_bfloat16 g_yl[(size_t)T_NUM * D_DIM];
__device__ __nv_bfloat16 g_wh[D_DIM * D_DIM];
__device__ __nv_bfloat16 g_wl[D_DIM * D_DIM];
__device__ float     g_dinv[O_NUM];
__device__ int       g_counts[O_NUM];
__device__ int       g_offs[O_NUM + 1];
__device__ int       g_cursor[O_NUM];
__device__ int       g_sorted[T_NUM];
__device__ int       g_part[NPART];
__device__ int       g_stride;
__device__ int       g_doff;

__device__ __forceinline__ int edge_src(const int* e32, int t, int stride) {
    return __ldg(e32 + (size_t)stride * t);
}
__device__ __forceinline__ int edge_dst(const int* e32, int t, int stride, int doff) {
    return __ldg(e32 + (size_t)stride * t + doff);
}
__device__ __forceinline__ const float* row_ptr(int k, const float* obj, const float* pred) {
    return (k < O_NUM) ? (obj + (size_t)k * D_DIM) : (pred + (size_t)(k - O_NUM) * D_DIM);
}

// ---------------- K1: prep = zero counters + W split + dtype detect ----------------
__global__ void prep_kernel(const float* __restrict__ W, const int* __restrict__ e32) {
    int b = blockIdx.x;
    if (b < NPART) {
        int i = b * 256 + threadIdx.x;
        if (i < O_NUM) { g_counts[i] = 0; g_cursor[i] = 0; }
    } else if (b < NPART + WBLK) {
        int i = (b - NPART) * 256 + threadIdx.x;
        float w = W[i];
        __nv_bfloat16 h = __float2bfloat16(w);
        g_wh[i] = h;
        g_wl[i] = __float2bfloat16(w - __bfloat162float(h));
    } else {
        if (threadIdx.x < 32) {
            int acc = 0;
            for (int i = threadIdx.x; i < 4096; i += 32) acc |= e32[2 * i + 1];
            #pragma unroll
            for (int off = 16; off; off >>= 1) acc |= __shfl_xor_sync(0xFFFFFFFFu, acc, off);
            if (threadIdx.x == 0) {
                g_stride = acc ? 2 : 4;
                g_doff   = acc ? 1 : 2;
            }
        }
    }
}

// ---------------- K2: histogram ----------------
__global__ void hist_kernel(const int* __restrict__ e32) {
    int t = blockIdx.x * blockDim.x + threadIdx.x;
    if (t < T_NUM) {
        int d = edge_dst(e32, t, g_stride, g_doff);
        atomicAdd(&g_counts[d], 1);
    }
}

// ---------------- K3: per-block exclusive scan ----------------
__global__ __launch_bounds__(256) void scan_block_kernel() {
    int t = threadIdx.x;
    int i = blockIdx.x * 256 + t;
    int lane = t & 31, w = t >> 5;
    int v = (i < O_NUM) ? g_counts[i] : 0;

    int iv = v;
    #pragma unroll
    for (int off = 1; off < 32; off <<= 1) {
        int n = __shfl_up_sync(0xFFFFFFFFu, iv, off);
        if (lane >= off) iv += n;
    }
    __shared__ int ws[8];
    if (lane == 31) ws[w] = iv;
    __syncthreads();
    if (w == 0 && lane < 8) {
        int x = ws[lane];
        #pragma unroll
        for (int off = 1; off < 8; off <<= 1) {
            int n = __shfl_up_sync(0x000000FFu, x, off);
            if (lane >= off) x += n;
        }
        ws[lane] = x;
    }
    __syncthreads();
    int excl = iv - v + (w ? ws[w - 1] : 0);
    if (i < O_NUM) g_offs[i] = excl;
    if (t == 255) g_part[blockIdx.x] = excl + v;
}

// ---------------- K4: fixup + dinv ----------------
__global__ __launch_bounds__(256) void scan_fix_kernel() {
    int b = blockIdx.x;
    int t = threadIdx.x;
    int lane = t & 31, w = t >> 5;

    int v = (t < b) ? g_part[t] : 0;
    #pragma unroll
    for (int off = 16; off; off >>= 1) v += __shfl_xor_sync(0xFFFFFFFFu, v, off);
    __shared__ int ws[8];
    if (lane == 0) ws[w] = v;
    __syncthreads();
    __shared__ int base_s;
    if (t == 0) {
        int s = 0;
        #pragma unroll
        for (int q = 0; q < 8; q++) s += ws[q];
        base_s = s;
    }
    __syncthreads();
    int base = base_s;

    int i = b * 256 + t;
    if (i < O_NUM) {
        g_offs[i] += base;
        g_dinv[i] = rsqrtf(2.0f + (float)g_counts[i]);
    }
    if (b == NPART - 1 && t == 0) g_offs[O_NUM] = base + g_part[NPART - 1];
}

// ---------------- K5: easy rows ----------------
__global__ __launch_bounds__(256) void agg_easy_kernel(const float* __restrict__ obj,
                                                       const float* __restrict__ pred,
                                                       const int* __restrict__ e32) {
    int gwarp = (blockIdx.x * blockDim.x + threadIdx.x) >> 5;
    int lane  = threadIdx.x & 31;
    if (gwarp >= T_NUM - O_NUM) return;
    int n = O_NUM + gwarp;

    const float4* xn = reinterpret_cast<const float4*>(pred + (size_t)gwarp * D_DIM);
    float4 a = __ldg(xn + lane);
    int s = edge_src(e32, n, g_stride);
    float ds = g_dinv[s];
    const float4* xs = reinterpret_cast<const float4*>(obj + (size_t)s * D_DIM);
    float4 v = __ldg(xs + lane);

    const float dn = RSQRT2F;
    float4 acc;
    acc.x = (fmaf(v.x, ds, a.x * dn)) * dn;
    acc.y = (fmaf(v.y, ds, a.y * dn)) * dn;
    acc.z = (fmaf(v.z, ds, a.z * dn)) * dn;
    acc.w = (fmaf(v.w, ds, a.w * dn)) * dn;

    float v4[4] = {acc.x, acc.y, acc.z, acc.w};
    alignas(8) __nv_bfloat16 h[4];
    alignas(8) __nv_bfloat16 l[4];
    #pragma unroll
    for (int q = 0; q < 4; q++) {
        h[q] = __float2bfloat16(v4[q]);
        l[q] = __float2bfloat16(v4[q] - __bfloat162float(h[q]));
    }
    size_t base = (size_t)n * D_DIM + lane * 4;
    *reinterpret_cast<uint2*>(g_yh + base) = *reinterpret_cast<const uint2*>(h);
    *reinterpret_cast<uint2*>(g_yl + base) = *reinterpret_cast<const uint2*>(l);
}

// ---------------- K6: counting-sort scatter ----------------
__global__ void csr_scatter_kernel(const int* __restrict__ e32) {
    int t = blockIdx.x * blockDim.x + threadIdx.x;
    if (t < T_NUM) {
        int d = edge_dst(e32, t, g_stride, g_doff);
        int pos = g_offs[d] + atomicAdd(&g_cursor[d], 1);
        g_sorted[pos] = t;
    }
}

// ---------------- K7: hard rows ----------------
__global__ __launch_bounds__(256) void agg_hard_kernel(const float* __restrict__ obj,
                                                       const float* __restrict__ pred,
                                                       const int* __restrict__ e32) {
    int n = (blockIdx.x * blockDim.x + threadIdx.x) >> 5;
    int lane  = threadIdx.x & 31;
    if (n >= O_NUM) return;
    float dn = g_dinv[n];

    const float4* xn = reinterpret_cast<const float4*>(obj + (size_t)n * D_DIM);
    float4 a = __ldg(xn + lane);

    int s = edge_src(e32, n, g_stride);
    float ds = g_dinv[s];
    const float4* xs = reinterpret_cast<const float4*>(obj + (size_t)s * D_DIM);
    float4 v1 = __ldg(xs + lane);

    float4 acc;
    acc.x = fmaf(v1.x, ds, a.x * dn);
    acc.y = fmaf(v1.y, ds, a.y * dn);
    acc.z = fmaf(v1.z, ds, a.z * dn);
    acc.w = fmaf(v1.w, ds, a.w * dn);

    int beg = g_offs[n];
    int cnt = g_offs[n + 1] - beg;
    for (int bb = 0; bb < cnt; bb += 8) {
        int m = cnt - bb; if (m > 8) m = 8;
        int   kid = 0;
        float dkl = 0.0f;
        if (lane < m) {
            kid = g_sorted[beg + bb + lane];
            dkl = (kid < O_NUM) ? g_dinv[kid] : RSQRT2F;
        }
        #pragma unroll
        for (int i = 0; i < 8; i++) {
            if (i >= m) break;
            int   k  = __shfl_sync(0xFFFFFFFFu, kid, i);
            float dk = __shfl_sync(0xFFFFFFFFu, dkl, i);
            const float4* xk = reinterpret_cast<const float4*>(row_ptr(k, obj, pred));
            float4 v = __ldg(xk + lane);
            acc.x = fmaf(v.x, dk, acc.x);
            acc.y = fmaf(v.y, dk, acc.y);
            acc.z = fmaf(v.z, dk, acc.z);
            acc.w = fmaf(v.w, dk, acc.w);
        }
    }

    acc.x *= dn; acc.y *= dn; acc.z *= dn; acc.w *= dn;

    float v4[4] = {acc.x, acc.y, acc.z, acc.w};
    alignas(8) __nv_bfloat16 h[4];
    alignas(8) __nv_bfloat16 l[4];
    #pragma unroll
    for (int i = 0; i < 4; i++) {
        h[i] = __float2bfloat16(v4[i]);
        l[i] = __float2bfloat16(v4[i] - __bfloat162float(h[i]));
    }
    size_t base = (size_t)n * D_DIM + lane * 4;
    *reinterpret_cast<uint2*>(g_yh + base) = *reinterpret_cast<const uint2*>(h);
    *reinterpret_cast<uint2*>(g_yl + base) = *reinterpret_cast<const uint2*>(l);
}

// ============ K8: persistent GEMM, W cached in registers ============
__device__ __forceinline__ void mma16816(float c[4], const uint32_t a[4], const uint32_t b[2]) {
    asm("mma.sync.aligned.m16n8k16.row.col.f32.bf16.bf16.f32 "
        "{%0,%1,%2,%3}, {%4,%5,%6,%7}, {%8,%9}, {%0,%1,%2,%3};"
        : "+f"(c[0]), "+f"(c[1]), "+f"(c[2]), "+f"(c[3])
        : "r"(a[0]), "r"(a[1]), "r"(a[2]), "r"(a[3]), "r"(b[0]), "r"(b[1]));
}

#define LDSY 136
#define TILE_M 32
#define SMEM_W_HALF (128 * LDSY)
#define SMEM_A_HALF (TILE_M * LDSY)
#define GEMM_SMEM_BYTES ((2 * SMEM_W_HALF + 4 * SMEM_A_HALF) * 2)   // 104448 B

#define NT_TILES ((N_NUM + TILE_M - 1) / TILE_M)    // 7813
#define GEMM_GRID 148

__device__ __forceinline__ uint32_t lds32(const __nv_bfloat16* p) {
    return *reinterpret_cast<const uint32_t*>(p);
}
__device__ __forceinline__ void cp_async16(uint32_t dst, const void* src) {
    asm volatile("cp.async.cg.shared.global [%0], [%1], 16;" :: "r"(dst), "l"(src));
}
#define CP_COMMIT() asm volatile("cp.async.commit_group;" ::: "memory")
#define CP_WAIT1()  asm volatile("cp.async.wait_group 1;" ::: "memory")

extern __shared__ char sm_raw[];

__global__ __launch_bounds__(512, 1) void gemm_wreg_kernel(const float* __restrict__ pred,
                                                           const float* __restrict__ bias,
                                                           float* __restrict__ out) {
    __nv_bfloat16* sWh = reinterpret_cast<__nv_bfloat16*>(sm_raw);
    __nv_bfloat16* sWl = sWh + SMEM_W_HALF;
    __nv_bfloat16* sA  = sWl + SMEM_W_HALF;

    int tid  = threadIdx.x;
    int warp = tid >> 5, lane = tid & 31;
    int g  = lane >> 2;
    int tg = lane & 3;
    int band = warp >> 3;
    int cg   = warp & 7;

    #pragma unroll
    for (int it = 0; it < 8; it++) {
        int idx = tid + it * 512;
        int half = idx >> 11;
        int r    = (idx >> 4) & 127;
        int seg  = idx & 15;
        const __nv_bfloat16* src = (half ? g_wl : g_wh) + r * D_DIM + seg * 8;
        __nv_bfloat16* dst = (half ? sWl : sWh) + r * LDSY + seg * 8;
        *reinterpret_cast<uint4*>(dst) = *reinterpret_cast<const uint4*>(src);
    }
    __syncthreads();

    uint32_t wfh[8][2][2], wfl[8][2][2];
    #pragma unroll
    for (int kt = 0; kt < 8; kt++) {
        #pragma unroll
        for (int n = 0; n < 2; n++) {
            int cw = cg * 16 + n * 8 + g;
            const __nv_bfloat16* pH = sWh + cw * LDSY + kt * 16 + tg * 2;
            const __nv_bfloat16* pL = sWl + cw * LDSY + kt * 16 + tg * 2;
            wfh[kt][n][0] = lds32(pH); wfh[kt][n][1] = lds32(pH + 8);
            wfl[kt][n][0] = lds32(pL); wfl[kt][n][1] = lds32(pL + 8);
        }
    }

    float2 bb[2];
    #pragma unroll
    for (int n = 0; n < 2; n++)
        bb[n] = __ldg(reinterpret_cast<const float2*>(bias + cg * 16 + n * 8 + tg * 2));

    uint32_t sA_u32 = (uint32_t)__cvta_generic_to_shared(sA);

    auto stage = [&](int tile, int buf) {
        int rowbase = tile * TILE_M;
        #pragma unroll
        for (int q = 0; q < 2; q++) {
            int idx = tid + q * 512;
            int half = idx >> 9;
            int r    = (idx >> 4) & 31;
            int seg  = idx & 15;
            int grow = rowbase + r;
            uint32_t off = ((buf * 2 + half) * SMEM_A_HALF + r * LDSY + seg * 8) * 2;
            if (grow < T_NUM) {
                const __nv_bfloat16* src = (half ? g_yl : g_yh) + (size_t)grow * D_DIM + seg * 8;
                cp_async16(sA_u32 + off, src);
            } else {
                alignas(16) __nv_bfloat16 v[8];
                if (grow < N_NUM) {
                    const float4* s = reinterpret_cast<const float4*>(
                        pred + (size_t)(grow - O_NUM) * D_DIM + seg * 8);
                    float4 f0 = __ldg(s), f1 = __ldg(s + 1);
                    float ff[8] = {f0.x, f0.y, f0.z, f0.w, f1.x, f1.y, f1.z, f1.w};
                    #pragma unroll
                    for (int p = 0; p < 8; p++) {
                        __nv_bfloat16 hh = __float2bfloat16(ff[p]);
                        v[p] = half ? __float2bfloat16(ff[p] - __bfloat162float(hh)) : hh;
                    }
                } else {
                    #pragma unroll
                    for (int p = 0; p < 8; p++) v[p] = __float2bfloat16(0.f);
                }
                *reinterpret_cast<uint4*>(reinterpret_cast<char*>(sA) + off) =
                    *reinterpret_cast<const uint4*>(v);
            }
        }
    };

    int t0 = blockIdx.x;
    if (t0 < NT_TILES) stage(t0, 0);
    CP_COMMIT();

    int buf = 0;
    for (int t = t0; t < NT_TILES; t += GEMM_GRID) {
        int tn = t + GEMM_GRID;
        if (tn < NT_TILES) stage(tn, buf ^ 1);
        CP_COMMIT();
        CP_WAIT1();
        __syncthreads();

        const __nv_bfloat16* bAh = sA + (buf * 2 + 0) * SMEM_A_HALF;
        const __nv_bfloat16* bAl = sA + (buf * 2 + 1) * SMEM_A_HALF;
        const __nv_bfloat16* aH0 = bAh + (band * 16 + g) * LDSY;
        const __nv_bfloat16* aL0 = bAl + (band * 16 + g) * LDSY;

        float c[2][4];
        #pragma unroll
        for (int n = 0; n < 2; n++)
            #pragma unroll
            for (int q = 0; q < 4; q++) c[n][q] = 0.0f;

        #pragma unroll
        for (int kt = 0; kt < 8; kt++) {
            int k = kt * 16;
            uint32_t ah[4], al[4];
            ah[0] = lds32(aH0 + k + tg * 2);
            ah[1] = lds32(aH0 + 8 * LDSY + k + tg * 2);
            ah[2] = lds32(aH0 + k + 8 + tg * 2);
            ah[3] = lds32(aH0 + 8 * LDSY + k + 8 + tg * 2);
            al[0] = lds32(aL0 + k + tg * 2);
            al[1] = lds32(aL0 + 8 * LDSY + k + tg * 2);
            al[2] = lds32(aL0 + k + 8 + tg * 2);
            al[3] = lds32(aL0 + 8 * LDSY + k + 8 + tg * 2);

            #pragma unroll
            for (int n = 0; n < 2; n++) {
                mma16816(c[n], ah, wfh[kt][n]);
                mma16816(c[n], al, wfh[kt][n]);
                mma16816(c[n], ah, wfl[kt][n]);
            }
        }

        int rowbase = t * TILE_M;
        int r0 = rowbase + band * 16 + g;
        int r1 = r0 + 8;
        #pragma unroll
        for (int n = 0; n < 2; n++) {
            int col = cg * 16 + n * 8 + tg * 2;
            if (r0 < N_NUM) {
                float2 o = make_float2(c[n][0] + bb[n].x, c[n][1] + bb[n].y);
                *reinterpret_cast<float2*>(out + (size_t)r0 * D_DIM + col) = o;
            }
            if (r1 < N_NUM) {
                float2 o = make_float2(c[n][2] + bb[n].x, c[n][3] + bb[n].y);
                *reinterpret_cast<float2*>(out + (size_t)r1 * D_DIM + col) = o;
            }
        }
        buf ^= 1;
        __syncthreads();
    }
}

// ---------------- launch: graph fork-join over two streams ----------------
static cudaStream_t g_s2 = nullptr;
static cudaEvent_t  g_evFork = nullptr, g_evJoin = nullptr;

extern "C" void kernel_launch(void* const* d_in, const int* in_sizes, int n_in,
                              void* d_out, int out_size) {
    const float* obj   = (const float*)d_in[0];
    const float* pred  = (const float*)d_in[1];
    const int*   e32   = (const int*)d_in[2];
    const float* W     = (const float*)d_in[3];
    const float* bias  = (const float*)d_in[4];
    float*       out   = (float*)d_out;

    if (g_s2 == nullptr) {   // one-time host-side setup (first call is uncaptured)
        cudaStreamCreateWithFlags(&g_s2, cudaStreamNonBlocking);
        cudaEventCreateWithFlags(&g_evFork, cudaEventDisableTiming);
        cudaEventCreateWithFlags(&g_evJoin, cudaEventDisableTiming);
        cudaFuncSetAttribute(gemm_wreg_kernel,
                             cudaFuncAttributeMaxDynamicSharedMemorySize, GEMM_SMEM_BYTES);
    }

    // serial prefix (stream 0)
    prep_kernel<<<NPART + WBLK + 1, 256>>>(W, e32);
    hist_kernel<<<(T_NUM + 255) / 256, 256>>>(e32);
    scan_block_kernel<<<NPART, 256>>>();
    scan_fix_kernel<<<NPART, 256>>>();

    // fork: branch A (stream 0) = agg_easy; branch B (s2) = scatter -> agg_hard
    cudaEventRecord(g_evFork, 0);
    cudaStreamWaitEvent(g_s2, g_evFork, 0);

    csr_scatter_kernel<<<(T_NUM + 255) / 256, 256, 0, g_s2>>>(e32);
    agg_hard_kernel<<<(O_NUM + 7) / 8, 256, 0, g_s2>>>(obj, pred, e32);
    cudaEventRecord(g_evJoin, g_s2);

    agg_easy_kernel<<<(T_NUM - O_NUM + 7) / 8, 256>>>(obj, pred, e32);

    // join, then GEMM
    cudaStreamWaitEvent(0, g_evJoin, 0);
    gemm_wreg_kernel<<<GEMM_GRID, 512, GEMM_SMEM_BYTES>>>(pred, bias, out);
}